// round 3
// baseline (speedup 1.0000x reference)
#include <cuda_runtime.h>
#include <math.h>

#define B   4096
#define L   200
#define LF  100
#define E   64
#define P   32
#define H   32
#define IFD 128
#define TPD 3168   /* P + PNET = 32 + 3136 */

// ---------------- scratch (device globals) ----------------
__device__ float g_prompt_input[B * E];
__device__ float g_total_prompt[(size_t)B * TPD];        // ~52 MB
__device__ float g_final_user[B * E];
__device__ float g_final_item[B * E];
__device__ float g_pos_pe[B * P];

// ======================================================================
// K1: gather + attention pooling + feature MLPs + prompt_input
// ======================================================================
__global__ __launch_bounds__(256) void k1_kernel(
    const float* __restrict__ item_emb, const float* __restrict__ user_emb,
    const float* __restrict__ W_if, const float* __restrict__ b_if,
    const float* __restrict__ W_uf, const float* __restrict__ b_uf,
    const float* __restrict__ item_features, const float* __restrict__ user_features,
    const int* __restrict__ user_id, const int* __restrict__ target_item_id,
    const int* __restrict__ history_item_id, const int* __restrict__ history_len,
    const int* __restrict__ item_pos_feedback, const int* __restrict__ pos_mask)
{
    int b = blockIdx.x;
    int tid = threadIdx.x;

    __shared__ float s_tgt[E];
    __shared__ float s_feat[IFD];
    __shared__ float s_ife[E];
    __shared__ float s_ufe[E];
    __shared__ float s_attn[L];
    __shared__ int   s_hidx[L];
    __shared__ int   s_pidx[LF];
    __shared__ float s_pm[LF];
    __shared__ float red[256];

    int tgt_id = target_item_id[b];
    if (tid < E)   s_tgt[tid]  = item_emb[(size_t)tgt_id * E + tid];
    if (tid < IFD) s_feat[tid] = item_features[(size_t)b * IFD + tid];
    for (int l = tid; l < L; l += 256)  s_hidx[l] = history_item_id[(size_t)b * L + l];
    for (int l = tid; l < LF; l += 256) {
        s_pidx[l] = item_pos_feedback[(size_t)b * LF + l];
        s_pm[l]   = pos_mask[(size_t)b * LF + l] ? 1.0f : 0.0f;
    }
    __syncthreads();

    // item feature MLP
    if (tid < E) {
        float a = b_if[tid];
        #pragma unroll 8
        for (int k = 0; k < IFD; k++) a += s_feat[k] * W_if[k * E + tid];
        s_ife[tid] = 1.0f / (1.0f + expf(-a));
    }
    __syncthreads();
    if (tid < IFD) s_feat[tid] = user_features[(size_t)b * IFD + tid];
    __syncthreads();
    if (tid < E) {
        float a = b_uf[tid];
        #pragma unroll 8
        for (int k = 0; k < IFD; k++) a += s_feat[k] * W_uf[k * E + tid];
        s_ufe[tid] = 1.0f / (1.0f + expf(-a));
    }
    __syncthreads();

    // attention scores
    int hlen = history_len[b];
    float sc = -1e30f;
    if (tid < L) {
        const float4* row = (const float4*)(item_emb + (size_t)s_hidx[tid] * E);
        float d = 0.0f;
        #pragma unroll
        for (int q = 0; q < 16; q++) {
            float4 v = row[q];
            d += v.x * s_tgt[4*q] + v.y * s_tgt[4*q+1] + v.z * s_tgt[4*q+2] + v.w * s_tgt[4*q+3];
        }
        sc = (tid < hlen) ? d * 0.125f : -1e9f;
    }
    red[tid] = sc; __syncthreads();
    for (int s = 128; s > 0; s >>= 1) { if (tid < s) red[tid] = fmaxf(red[tid], red[tid+s]); __syncthreads(); }
    float mx = red[0]; __syncthreads();
    float ex = (tid < L) ? expf(sc - mx) : 0.0f;
    red[tid] = ex; __syncthreads();
    for (int s = 128; s > 0; s >>= 1) { if (tid < s) red[tid] += red[tid+s]; __syncthreads(); }
    float inv = 1.0f / red[0];
    __syncthreads();
    if (tid < L) s_attn[tid] = ex * inv;
    __syncthreads();

    // ---- history pooling: 4 groups x 64 lanes ----
    int g = tid >> 6, e = tid & 63;
    {
        float acc = 0.0f;
        int base = g * 50;
        #pragma unroll 5
        for (int l = base; l < base + 50; l++)
            acc += s_attn[l] * item_emb[(size_t)s_hidx[l] * E + e];
        red[tid] = acc;
    }
    __syncthreads();
    if (tid < 64) {
        float hp = red[tid] + red[64 + tid] + red[128 + tid] + red[192 + tid];
        int uid = user_id[b];
        g_final_user[b * E + tid] = user_emb[(size_t)uid * E + tid] + s_ufe[tid] + hp;
        g_final_item[b * E + tid] = s_tgt[tid] + s_ife[tid];
    }
    __syncthreads();

    // ---- prompt pooling: 4 groups x 64 lanes ----
    {
        float pacc = 0.0f;
        int base = g * 25;
        #pragma unroll 5
        for (int l = base; l < base + 25; l++)
            pacc += s_pm[l] * item_emb[(size_t)s_pidx[l] * E + e];
        red[tid] = pacc;
    }
    __syncthreads();
    if (tid < 64) {
        float s = red[tid] + red[64 + tid] + red[128 + tid] + red[192 + tid];
        float cnt = 0.0f;
        #pragma unroll 10
        for (int l = 0; l < LF; l++) cnt += s_pm[l];
        g_prompt_input[b * E + tid] = s / cnt;
    }
}

// ======================================================================
// K2: total_prompt = relu(prompt_input[B,64] @ Wp[64,3168] + bp)
// ======================================================================
__global__ __launch_bounds__(256) void k2_kernel(
    const float* __restrict__ Wp, const float* __restrict__ bp)
{
    int b0 = blockIdx.x * 64;
    int jb = blockIdx.y * 792;
    __shared__ float sA[64 * 64];
    for (int t = threadIdx.x; t < 64 * 64; t += 256)
        sA[t] = g_prompt_input[(b0 + (t >> 6)) * E + (t & 63)];
    __syncthreads();

    for (int t = threadIdx.x; t < 4 * 792; t += 256) {
        int rg = t / 792;
        int j  = jb + (t - rg * 792);
        float acc[16];
        #pragma unroll
        for (int r = 0; r < 16; r++) acc[r] = 0.0f;
        const float* wcol = Wp + j;
        #pragma unroll 4
        for (int k = 0; k < 64; k++) {
            float w = wcol[(size_t)k * TPD];
            #pragma unroll
            for (int r = 0; r < 16; r++) acc[r] += sA[(rg * 16 + r) * 64 + k] * w;
        }
        float bb = bp[j];
        #pragma unroll
        for (int r = 0; r < 16; r++) {
            float v = acc[r] + bb;
            g_total_prompt[(size_t)(b0 + rg * 16 + r) * TPD + j] = v > 0.0f ? v : 0.0f;
        }
    }
}

// ======================================================================
// K3 v2: per-sample prompt MLP, vectorized smem (transposed weights)
//   smem pool layout (floats):
//     W1T [32 x 68]  @ 0        (w1T[p*68+e])
//     W2T [32 x 36]  @ 2176     (w2T[p*36+h])
//     US  [8 x 68]   @ 3328
//     HS  [8 x 36]   @ 3872
//     B1  [32]       @ 4160
//     B2  [32]       @ 4192
//     RED [256]      @ 4224
//     PE  [64]       @ 4480
// ======================================================================
#define W1T_OFF 0
#define W2T_OFF 2176
#define US_OFF  3328
#define HS_OFF  3872
#define B1_OFF  4160
#define B2_OFF  4192
#define RED_OFF 4224
#define PE_OFF  4480
#define SM_SIZE 4544

__global__ __launch_bounds__(256) void k3_kernel(
    const float* __restrict__ item_emb,
    const int* __restrict__ pos_fb, const int* __restrict__ pos_mask,
    const int* __restrict__ neg_fb, const int* __restrict__ neg_mask,
    float* __restrict__ out)
{
    int b = blockIdx.x;
    int tid = threadIdx.x;
    const float* tp = g_total_prompt + (size_t)b * TPD;

    __shared__ __align__(16) float sm[SM_SIZE];
    __shared__ int   s_fi[104];
    __shared__ float s_fm[104];

    float* W1T = sm + W1T_OFF;
    float* W2T = sm + W2T_OFF;
    float* US  = sm + US_OFF;
    float* HS  = sm + HS_OFF;
    float* B1  = sm + B1_OFF;
    float* B2  = sm + B2_OFF;
    float* RED = sm + RED_OFF;
    float* PE  = sm + PE_OFF;

    // load + transpose w1 (w1[e][h] = tp[32 + e*32 + h]) -> W1T[h*68 + e]
    for (int t = tid; t < 2048; t += 256) {
        int e = t >> 5, h = t & 31;
        W1T[h * 68 + e] = tp[32 + t];
    }
    // load + transpose w2 (w2[h][p] = tp[2112 + h*32 + p]) -> W2T[p*36 + h]
    for (int t = tid; t < 1024; t += 256) {
        int h = t >> 5, p = t & 31;
        W2T[p * 36 + h] = tp[2112 + t];
    }
    if (tid < 32) { B1[tid] = tp[2080 + tid]; B2[tid] = tp[3136 + tid]; }

    int i = tid >> 5;     // item slot / warp id (0..7)
    int p = tid & 31;     // output unit

    for (int br = 0; br < 2; br++) {
        const int* fb = br ? neg_fb : pos_fb;
        const int* mk = br ? neg_mask : pos_mask;
        __syncthreads();
        if (tid < 104) {
            int v = 0; float m = 0.0f;
            if (tid < LF) { v = fb[(size_t)b * LF + tid]; m = mk[(size_t)b * LF + tid] ? 1.0f : 0.0f; }
            s_fi[tid] = v; s_fm[tid] = m;
        }
        __syncthreads();

        float acc = 0.0f;
        for (int g = 0; g < 13; g++) {
            // gather 8 item rows: warp i loads row for slot i, float2 per lane
            {
                int idx = s_fi[g * 8 + i];
                const float2* src = (const float2*)(item_emb + (size_t)idx * E);
                *(float2*)&US[i * 68 + 2 * p] = src[p];
            }
            __syncthreads();

            // layer 1: hv_p = b1[p] + sum_e u[e]*w1[e][p]
            float hv = B1[p];
            const float4* wrow = (const float4*)&W1T[p * 68];
            const float4* urow = (const float4*)&US[i * 68];
            #pragma unroll
            for (int c = 0; c < 16; c++) {
                float4 w = wrow[c], u = urow[c];
                hv += u.x * w.x + u.y * w.y + u.z * w.z + u.w * w.w;
            }
            HS[i * 36 + p] = hv > 0.0f ? hv : 0.0f;
            __syncthreads();

            // layer 2: ov_p = b2[p] + sum_h hs[h]*w2[h][p]
            float ov = B2[p];
            const float4* w2row = (const float4*)&W2T[p * 36];
            const float4* hrow  = (const float4*)&HS[i * 36];
            #pragma unroll
            for (int c = 0; c < 8; c++) {
                float4 w = w2row[c], h4 = hrow[c];
                ov += h4.x * w.x + h4.y * w.y + h4.z * w.z + h4.w * w.w;
            }
            acc += s_fm[g * 8 + i] * ov;
            __syncthreads();
        }
        RED[tid] = acc;
        __syncthreads();
        if (tid < 32) {
            float s = 0.0f;
            #pragma unroll
            for (int q = 0; q < 8; q++) s += RED[q * 32 + tid];
            PE[br * 32 + tid] = s;
        }
    }
    __syncthreads();

    if (tid < 32) {
        float pos = PE[tid], neg = PE[32 + tid];
        g_pos_pe[b * 32 + tid] = pos;
        float x = neg - pos;  // softplus(-(pos-neg)) == softplus(neg-pos)
        out[B + b * 32 + tid] = fmaxf(x, 0.0f) + log1pf(expf(-fabsf(x)));
    }
}

// ======================================================================
// K4 v2: fusion MLP (128->200->80->64) + dot. 16 rows per block.
// ======================================================================
__global__ __launch_bounds__(256) void k4_kernel(
    const float* __restrict__ Wf1, const float* __restrict__ bf1,
    const float* __restrict__ Wf2, const float* __restrict__ bf2,
    const float* __restrict__ Wf3, float* __restrict__ out)
{
    int b0 = blockIdx.x * 16;
    int tid = threadIdx.x;
    __shared__ float fin[16 * 128];
    __shared__ float h1[16 * 200];
    __shared__ float h2[16 * 80];
    __shared__ float fu[16 * 64];

    for (int t = tid; t < 16 * 128; t += 256) {
        int r = t >> 7, c = t & 127;
        int bb = b0 + r;
        float v;
        if (c < 64)      v = g_final_item[bb * 64 + c];
        else if (c < 96) v = g_pos_pe[bb * 32 + (c - 64)];
        else             v = g_total_prompt[(size_t)bb * TPD + (c - 96)];
        fin[t] = v;
    }
    __syncthreads();

    if (tid < 200) {
        float acc[16];
        float bb1 = bf1[tid];
        #pragma unroll
        for (int r = 0; r < 16; r++) acc[r] = bb1;
        #pragma unroll 2
        for (int k = 0; k < 128; k++) {
            float w = Wf1[k * 200 + tid];
            #pragma unroll
            for (int r = 0; r < 16; r++) acc[r] += fin[r * 128 + k] * w;
        }
        #pragma unroll
        for (int r = 0; r < 16; r++) h1[r * 200 + tid] = acc[r] > 0.0f ? acc[r] : 0.0f;
    }
    __syncthreads();

    if (tid < 80) {
        float acc[16];
        float bb2 = bf2[tid];
        #pragma unroll
        for (int r = 0; r < 16; r++) acc[r] = bb2;
        #pragma unroll 2
        for (int k = 0; k < 200; k++) {
            float w = Wf2[k * 80 + tid];
            #pragma unroll
            for (int r = 0; r < 16; r++) acc[r] += h1[r * 200 + k] * w;
        }
        #pragma unroll
        for (int r = 0; r < 16; r++) h2[r * 80 + tid] = acc[r] > 0.0f ? acc[r] : 0.0f;
    }
    __syncthreads();

    if (tid < 64) {
        float acc[16];
        #pragma unroll
        for (int r = 0; r < 16; r++) acc[r] = 0.0f;
        #pragma unroll 2
        for (int k = 0; k < 80; k++) {
            float w = Wf3[k * 64 + tid];
            #pragma unroll
            for (int r = 0; r < 16; r++) acc[r] += h2[r * 80 + k] * w;
        }
        #pragma unroll
        for (int r = 0; r < 16; r++) fu[r * 64 + tid] = acc[r];
    }
    __syncthreads();

    // each warp handles 2 rows
    int wid = tid >> 5, lane = tid & 31;
    #pragma unroll
    for (int rr = 0; rr < 2; rr++) {
        int r = wid * 2 + rr;
        int bb = b0 + r;
        float par = g_final_user[bb * 64 + lane]      * fu[r * 64 + lane]
                  + g_final_user[bb * 64 + 32 + lane] * fu[r * 64 + 32 + lane];
        #pragma unroll
        for (int s = 16; s > 0; s >>= 1) par += __shfl_xor_sync(0xffffffff, par, s);
        if (lane == 0) out[bb] = par;
    }
}

// ======================================================================
extern "C" void kernel_launch(void* const* d_in, const int* in_sizes, int n_in,
                              void* d_out, int out_size)
{
    const float* item_emb        = (const float*)d_in[0];
    const float* user_emb        = (const float*)d_in[1];
    const float* W_if            = (const float*)d_in[2];
    const float* b_if            = (const float*)d_in[3];
    const float* W_uf            = (const float*)d_in[4];
    const float* b_uf            = (const float*)d_in[5];
    const float* Wp              = (const float*)d_in[6];
    const float* bp              = (const float*)d_in[7];
    const float* Wf1             = (const float*)d_in[8];
    const float* bf1             = (const float*)d_in[9];
    const float* Wf2             = (const float*)d_in[10];
    const float* bf2             = (const float*)d_in[11];
    const float* Wf3             = (const float*)d_in[12];
    const float* item_features   = (const float*)d_in[13];
    const float* user_features   = (const float*)d_in[14];
    const int*   user_id         = (const int*)d_in[15];
    const int*   target_item_id  = (const int*)d_in[16];
    const int*   history_item_id = (const int*)d_in[17];
    const int*   history_len     = (const int*)d_in[18];
    const int*   pos_fb          = (const int*)d_in[19];
    const int*   pos_mask        = (const int*)d_in[20];
    const int*   neg_fb          = (const int*)d_in[21];
    const int*   neg_mask        = (const int*)d_in[22];
    float* out = (float*)d_out;

    k1_kernel<<<B, 256>>>(item_emb, user_emb, W_if, b_if, W_uf, b_uf,
                          item_features, user_features, user_id, target_item_id,
                          history_item_id, history_len, pos_fb, pos_mask);
    k2_kernel<<<dim3(64, 4), 256>>>(Wp, bp);
    k3_kernel<<<B, 256>>>(item_emb, pos_fb, pos_mask, neg_fb, neg_mask, out);
    k4_kernel<<<B / 16, 256>>>(Wf1, bf1, Wf2, bf2, Wf3, out);
}

// round 5
// speedup vs baseline: 1.6147x; 1.6147x over previous
#include <cuda_runtime.h>
#include <math.h>

#define B   4096
#define L   200
#define LF  100
#define E   64
#define P   32
#define H   32
#define IFD 128
#define TPD 3168   /* P + PNET = 32 + 3136 */

// ---------------- scratch (device globals) ----------------
__device__ float g_prompt_input[B * E];
__device__ float g_total_prompt[(size_t)B * TPD];        // ~52 MB
__device__ float g_final_user[B * E];
__device__ float g_final_item[B * E];
__device__ float g_pos_pe[B * P];

// ======================================================================
// K1: gather + attention pooling + feature MLPs + prompt_input
// ======================================================================
__global__ __launch_bounds__(256) void k1_kernel(
    const float* __restrict__ item_emb, const float* __restrict__ user_emb,
    const float* __restrict__ W_if, const float* __restrict__ b_if,
    const float* __restrict__ W_uf, const float* __restrict__ b_uf,
    const float* __restrict__ item_features, const float* __restrict__ user_features,
    const int* __restrict__ user_id, const int* __restrict__ target_item_id,
    const int* __restrict__ history_item_id, const int* __restrict__ history_len,
    const int* __restrict__ item_pos_feedback, const int* __restrict__ pos_mask)
{
    int b = blockIdx.x;
    int tid = threadIdx.x;

    __shared__ float s_tgt[E];
    __shared__ float s_feat[IFD];
    __shared__ float s_ife[E];
    __shared__ float s_ufe[E];
    __shared__ float s_attn[L];
    __shared__ int   s_hidx[L];
    __shared__ int   s_pidx[LF];
    __shared__ float s_pm[LF];
    __shared__ float red[256];

    int tgt_id = target_item_id[b];
    if (tid < E)   s_tgt[tid]  = item_emb[(size_t)tgt_id * E + tid];
    if (tid < IFD) s_feat[tid] = item_features[(size_t)b * IFD + tid];
    for (int l = tid; l < L; l += 256)  s_hidx[l] = history_item_id[(size_t)b * L + l];
    for (int l = tid; l < LF; l += 256) {
        s_pidx[l] = item_pos_feedback[(size_t)b * LF + l];
        s_pm[l]   = pos_mask[(size_t)b * LF + l] ? 1.0f : 0.0f;
    }
    __syncthreads();

    if (tid < E) {
        float a = b_if[tid];
        #pragma unroll 8
        for (int k = 0; k < IFD; k++) a += s_feat[k] * W_if[k * E + tid];
        s_ife[tid] = 1.0f / (1.0f + expf(-a));
    }
    __syncthreads();
    if (tid < IFD) s_feat[tid] = user_features[(size_t)b * IFD + tid];
    __syncthreads();
    if (tid < E) {
        float a = b_uf[tid];
        #pragma unroll 8
        for (int k = 0; k < IFD; k++) a += s_feat[k] * W_uf[k * E + tid];
        s_ufe[tid] = 1.0f / (1.0f + expf(-a));
    }
    __syncthreads();

    int hlen = history_len[b];
    float sc = -1e30f;
    if (tid < L) {
        const float4* row = (const float4*)(item_emb + (size_t)s_hidx[tid] * E);
        float d = 0.0f;
        #pragma unroll
        for (int q = 0; q < 16; q++) {
            float4 v = row[q];
            d += v.x * s_tgt[4*q] + v.y * s_tgt[4*q+1] + v.z * s_tgt[4*q+2] + v.w * s_tgt[4*q+3];
        }
        sc = (tid < hlen) ? d * 0.125f : -1e9f;
    }
    red[tid] = sc; __syncthreads();
    for (int s = 128; s > 0; s >>= 1) { if (tid < s) red[tid] = fmaxf(red[tid], red[tid+s]); __syncthreads(); }
    float mx = red[0]; __syncthreads();
    float ex = (tid < L) ? expf(sc - mx) : 0.0f;
    red[tid] = ex; __syncthreads();
    for (int s = 128; s > 0; s >>= 1) { if (tid < s) red[tid] += red[tid+s]; __syncthreads(); }
    float inv = 1.0f / red[0];
    __syncthreads();
    if (tid < L) s_attn[tid] = ex * inv;
    __syncthreads();

    int g = tid >> 6, e = tid & 63;
    {
        float acc = 0.0f;
        int base = g * 50;
        #pragma unroll 5
        for (int l = base; l < base + 50; l++)
            acc += s_attn[l] * item_emb[(size_t)s_hidx[l] * E + e];
        red[tid] = acc;
    }
    __syncthreads();
    if (tid < 64) {
        float hp = red[tid] + red[64 + tid] + red[128 + tid] + red[192 + tid];
        int uid = user_id[b];
        g_final_user[b * E + tid] = user_emb[(size_t)uid * E + tid] + s_ufe[tid] + hp;
        g_final_item[b * E + tid] = s_tgt[tid] + s_ife[tid];
    }
    __syncthreads();

    {
        float pacc = 0.0f;
        int base = g * 25;
        #pragma unroll 5
        for (int l = base; l < base + 25; l++)
            pacc += s_pm[l] * item_emb[(size_t)s_pidx[l] * E + e];
        red[tid] = pacc;
    }
    __syncthreads();
    if (tid < 64) {
        float s = red[tid] + red[64 + tid] + red[128 + tid] + red[192 + tid];
        float cnt = 0.0f;
        #pragma unroll 10
        for (int l = 0; l < LF; l++) cnt += s_pm[l];
        g_prompt_input[b * E + tid] = s / cnt;
    }
}

// ======================================================================
// K2: total_prompt = relu(prompt_input[B,64] @ Wp[64,3168] + bp)
// ======================================================================
__global__ __launch_bounds__(256) void k2_kernel(
    const float* __restrict__ Wp, const float* __restrict__ bp)
{
    int b0 = blockIdx.x * 64;
    int jb = blockIdx.y * 792;
    __shared__ float sA[64 * 64];
    for (int t = threadIdx.x; t < 64 * 64; t += 256)
        sA[t] = g_prompt_input[(b0 + (t >> 6)) * E + (t & 63)];
    __syncthreads();

    for (int t = threadIdx.x; t < 4 * 792; t += 256) {
        int rg = t / 792;
        int j  = jb + (t - rg * 792);
        float acc[16];
        #pragma unroll
        for (int r = 0; r < 16; r++) acc[r] = 0.0f;
        const float* wcol = Wp + j;
        #pragma unroll 4
        for (int k = 0; k < 64; k++) {
            float w = wcol[(size_t)k * TPD];
            #pragma unroll
            for (int r = 0; r < 16; r++) acc[r] += sA[(rg * 16 + r) * 64 + k] * w;
        }
        float bb = bp[j];
        #pragma unroll
        for (int r = 0; r < 16; r++) {
            float v = acc[r] + bb;
            g_total_prompt[(size_t)(b0 + rg * 16 + r) * TPD + j] = v > 0.0f ? v : 0.0f;
        }
    }
}

// ======================================================================
// K3 v3b: register-tiled per-sample prompt MLP (alignment fixed).
//   thread (ig, pg): 4 items x 4 units tile. 26 ig x 8 pg = 208 active.
// ======================================================================
#define NI   104
#define UTS  104   /* UT row stride (multiple of 4 for float4) */
#define HTS  108   /* HT row stride (multiple of 4 for float4) */

__global__ __launch_bounds__(256) void k3_kernel(
    const float* __restrict__ item_emb,
    const int* __restrict__ pos_fb, const int* __restrict__ pos_mask,
    const int* __restrict__ neg_fb, const int* __restrict__ neg_mask,
    float* __restrict__ out)
{
    int b = blockIdx.x;
    int tid = threadIdx.x;
    const float* tp = g_total_prompt + (size_t)b * TPD;

    __shared__ __align__(16) float W1[E * H];        // w1[e][h], natural
    __shared__ __align__(16) float W2[H * P];        // w2[h][p], natural
    __shared__ __align__(16) float UT[32 * UTS];     // u chunk transposed
    __shared__ __align__(16) float HT[H * HTS];      // hidden transposed
    __shared__ float B1[H];
    __shared__ float B2[P];
    __shared__ int   s_fi[NI];
    __shared__ float s_fm[NI];
    __shared__ float RED[26 * 32];
    __shared__ float PE[64];

    for (int t = tid; t < 2048; t += 256) W1[t] = tp[32 + t];
    for (int t = tid; t < 1024; t += 256) W2[t] = tp[2112 + t];
    if (tid < 32) { B1[tid] = tp[2080 + tid]; B2[tid] = tp[3136 + tid]; }

    int pg = tid & 7;        // unit group (0..7)
    int ig = tid >> 3;       // item group (0..31; active < 26)
    bool act = (ig < 26);
    int p0 = pg * 4;
    int i0 = ig * 4;

    for (int br = 0; br < 2; br++) {
        const int* fb = br ? neg_fb : pos_fb;
        const int* mk = br ? neg_mask : pos_mask;
        __syncthreads();
        if (tid < NI) {
            int v = 0; float m = 0.0f;
            if (tid < LF) { v = fb[(size_t)b * LF + tid]; m = mk[(size_t)b * LF + tid] ? 1.0f : 0.0f; }
            s_fi[tid] = v; s_fm[tid] = m;
        }
        __syncthreads();

        // ---------- layer 1: acc1[ii][pp] over e in 2 chunks ----------
        float acc1[16];
        #pragma unroll
        for (int ii = 0; ii < 4; ii++)
            #pragma unroll
            for (int pp = 0; pp < 4; pp++) acc1[ii*4+pp] = B1[p0 + pp];

        #pragma unroll
        for (int ch = 0; ch < 2; ch++) {
            // transpose-load: UT[le][i] = u[i][ch*32+le]
            for (int idx = tid; idx < NI * 8; idx += 256) {
                int c4 = idx / NI;
                int i  = idx - c4 * NI;
                const float4 v = *(const float4*)(item_emb + (size_t)s_fi[i] * E + ch * 32 + c4 * 4);
                UT[(c4 * 4 + 0) * UTS + i] = v.x;
                UT[(c4 * 4 + 1) * UTS + i] = v.y;
                UT[(c4 * 4 + 2) * UTS + i] = v.z;
                UT[(c4 * 4 + 3) * UTS + i] = v.w;
            }
            __syncthreads();
            if (act) {
                #pragma unroll
                for (int le = 0; le < 32; le++) {
                    int e = ch * 32 + le;
                    float4 w = *(const float4*)&W1[e * H + p0];
                    float4 u = *(const float4*)&UT[le * UTS + i0];
                    acc1[0]  += u.x * w.x; acc1[1]  += u.x * w.y; acc1[2]  += u.x * w.z; acc1[3]  += u.x * w.w;
                    acc1[4]  += u.y * w.x; acc1[5]  += u.y * w.y; acc1[6]  += u.y * w.z; acc1[7]  += u.y * w.w;
                    acc1[8]  += u.z * w.x; acc1[9]  += u.z * w.y; acc1[10] += u.z * w.z; acc1[11] += u.z * w.w;
                    acc1[12] += u.w * w.x; acc1[13] += u.w * w.y; acc1[14] += u.w * w.z; acc1[15] += u.w * w.w;
                }
            }
            __syncthreads();
        }

        // relu + write HT[p][i] (HTS multiple of 4 -> aligned float4)
        if (act) {
            #pragma unroll
            for (int pp = 0; pp < 4; pp++) {
                float4 hv;
                hv.x = fmaxf(acc1[0*4+pp], 0.0f);
                hv.y = fmaxf(acc1[1*4+pp], 0.0f);
                hv.z = fmaxf(acc1[2*4+pp], 0.0f);
                hv.w = fmaxf(acc1[3*4+pp], 0.0f);
                *(float4*)&HT[(p0 + pp) * HTS + i0] = hv;
            }
        }
        __syncthreads();

        // ---------- layer 2 + masked sum ----------
        float acc2[16];
        #pragma unroll
        for (int ii = 0; ii < 4; ii++)
            #pragma unroll
            for (int pp = 0; pp < 4; pp++) acc2[ii*4+pp] = B2[p0 + pp];
        if (act) {
            #pragma unroll
            for (int h = 0; h < 32; h++) {
                float4 w = *(const float4*)&W2[h * P + p0];
                float4 hh = *(const float4*)&HT[h * HTS + i0];
                acc2[0]  += hh.x * w.x; acc2[1]  += hh.x * w.y; acc2[2]  += hh.x * w.z; acc2[3]  += hh.x * w.w;
                acc2[4]  += hh.y * w.x; acc2[5]  += hh.y * w.y; acc2[6]  += hh.y * w.z; acc2[7]  += hh.y * w.w;
                acc2[8]  += hh.z * w.x; acc2[9]  += hh.z * w.y; acc2[10] += hh.z * w.z; acc2[11] += hh.z * w.w;
                acc2[12] += hh.w * w.x; acc2[13] += hh.w * w.y; acc2[14] += hh.w * w.z; acc2[15] += hh.w * w.w;
            }
            float part[4] = {0.0f, 0.0f, 0.0f, 0.0f};
            #pragma unroll
            for (int ii = 0; ii < 4; ii++) {
                float m = s_fm[i0 + ii];
                #pragma unroll
                for (int pp = 0; pp < 4; pp++) part[pp] += m * acc2[ii*4+pp];
            }
            #pragma unroll
            for (int pp = 0; pp < 4; pp++) RED[ig * 32 + p0 + pp] = part[pp];
        }
        __syncthreads();

        if (tid < 32) {
            float s = 0.0f;
            #pragma unroll
            for (int q = 0; q < 26; q++) s += RED[q * 32 + tid];
            PE[br * 32 + tid] = s;
        }
    }
    __syncthreads();

    if (tid < 32) {
        float pos = PE[tid], neg = PE[32 + tid];
        g_pos_pe[b * 32 + tid] = pos;
        float x = neg - pos;  // softplus(-(pos-neg)) == softplus(neg-pos)
        out[B + b * 32 + tid] = fmaxf(x, 0.0f) + log1pf(expf(-fabsf(x)));
    }
}

// ======================================================================
// K4: fusion MLP (128->200->80->64) + dot. 8 rows/block (R2 version).
// ======================================================================
__global__ __launch_bounds__(256) void k4_kernel(
    const float* __restrict__ Wf1, const float* __restrict__ bf1,
    const float* __restrict__ Wf2, const float* __restrict__ bf2,
    const float* __restrict__ Wf3, float* __restrict__ out)
{
    int b0 = blockIdx.x * 8;
    int tid = threadIdx.x;
    __shared__ float fin[8 * 128];
    __shared__ float h1[8 * 200];
    __shared__ float h2[8 * 80];
    __shared__ float fu[8 * 64];

    for (int t = tid; t < 8 * 128; t += 256) {
        int r = t >> 7, c = t & 127;
        int bb = b0 + r;
        float v;
        if (c < 64)      v = g_final_item[bb * 64 + c];
        else if (c < 96) v = g_pos_pe[bb * 32 + (c - 64)];
        else             v = g_total_prompt[(size_t)bb * TPD + (c - 96)];
        fin[t] = v;
    }
    __syncthreads();

    if (tid < 200) {
        float acc[8];
        #pragma unroll
        for (int r = 0; r < 8; r++) acc[r] = bf1[tid];
        for (int k = 0; k < 128; k++) {
            float w = Wf1[k * 200 + tid];
            #pragma unroll
            for (int r = 0; r < 8; r++) acc[r] += fin[r * 128 + k] * w;
        }
        #pragma unroll
        for (int r = 0; r < 8; r++) h1[r * 200 + tid] = acc[r] > 0.0f ? acc[r] : 0.0f;
    }
    __syncthreads();

    if (tid < 80) {
        float acc[8];
        #pragma unroll
        for (int r = 0; r < 8; r++) acc[r] = bf2[tid];
        for (int k = 0; k < 200; k++) {
            float w = Wf2[k * 80 + tid];
            #pragma unroll
            for (int r = 0; r < 8; r++) acc[r] += h1[r * 200 + k] * w;
        }
        #pragma unroll
        for (int r = 0; r < 8; r++) h2[r * 80 + tid] = acc[r] > 0.0f ? acc[r] : 0.0f;
    }
    __syncthreads();

    if (tid < 64) {
        float acc[8];
        #pragma unroll
        for (int r = 0; r < 8; r++) acc[r] = 0.0f;
        for (int k = 0; k < 80; k++) {
            float w = Wf3[k * 64 + tid];
            #pragma unroll
            for (int r = 0; r < 8; r++) acc[r] += h2[r * 80 + k] * w;
        }
        #pragma unroll
        for (int r = 0; r < 8; r++) fu[r * 64 + tid] = acc[r];
    }
    __syncthreads();

    int r = tid >> 5, lane = tid & 31;
    int bb = b0 + r;
    float par = g_final_user[bb * 64 + lane]      * fu[r * 64 + lane]
              + g_final_user[bb * 64 + 32 + lane] * fu[r * 64 + 32 + lane];
    #pragma unroll
    for (int s = 16; s > 0; s >>= 1) par += __shfl_xor_sync(0xffffffff, par, s);
    if (lane == 0) out[bb] = par;
}

// ======================================================================
extern "C" void kernel_launch(void* const* d_in, const int* in_sizes, int n_in,
                              void* d_out, int out_size)
{
    const float* item_emb        = (const float*)d_in[0];
    const float* user_emb        = (const float*)d_in[1];
    const float* W_if            = (const float*)d_in[2];
    const float* b_if            = (const float*)d_in[3];
    const float* W_uf            = (const float*)d_in[4];
    const float* b_uf            = (const float*)d_in[5];
    const float* Wp              = (const float*)d_in[6];
    const float* bp              = (const float*)d_in[7];
    const float* Wf1             = (const float*)d_in[8];
    const float* bf1             = (const float*)d_in[9];
    const float* Wf2             = (const float*)d_in[10];
    const float* bf2             = (const float*)d_in[11];
    const float* Wf3             = (const float*)d_in[12];
    const float* item_features   = (const float*)d_in[13];
    const float* user_features   = (const float*)d_in[14];
    const int*   user_id         = (const int*)d_in[15];
    const int*   target_item_id  = (const int*)d_in[16];
    const int*   history_item_id = (const int*)d_in[17];
    const int*   history_len     = (const int*)d_in[18];
    const int*   pos_fb          = (const int*)d_in[19];
    const int*   pos_mask        = (const int*)d_in[20];
    const int*   neg_fb          = (const int*)d_in[21];
    const int*   neg_mask        = (const int*)d_in[22];
    float* out = (float*)d_out;

    k1_kernel<<<B, 256>>>(item_emb, user_emb, W_if, b_if, W_uf, b_uf,
                          item_features, user_features, user_id, target_item_id,
                          history_item_id, history_len, pos_fb, pos_mask);
    k2_kernel<<<dim3(64, 4), 256>>>(Wp, bp);
    k3_kernel<<<B, 256>>>(item_emb, pos_fb, pos_mask, neg_fb, neg_mask, out);
    k4_kernel<<<B / 8, 256>>>(Wf1, bf1, Wf2, bf2, Wf3, out);
}